// round 1
// baseline (speedup 1.0000x reference)
#include <cuda_runtime.h>
#include <math.h>
#include <stdint.h>

// Problem dims
#define BB   32
#define LL   1024
#define VV   64
#define PLn  16
#define PHn  64
#define PFn  32
#define DD   128
#define HH   256
#define KK   1024
#define NVQ  (BB*VV*PFn)   // 65536 vq rows
#define NROW (BB*VV*DD)    // 262144 mlp rows

// ---------------- scratch (device globals; no allocation allowed) ----------
__device__ float g_mean[BB*VV];
__device__ float g_std[BB*VV];
__device__ float g_A[(size_t)NROW*PHn];     // MLP input, [row=(b,v,d)][p]   64MB
__device__ float g_Zp[(size_t)NVQ*DD];      // z_p  [n=(b,v,f)][d]           32MB
__device__ float g_Zcode[(size_t)NVQ*DD];   // z_code                        32MB
__device__ float g_c2[KK];

// packed fp32x2 FMA (FFMA2) — 2x fp32 throughput on sm_103a
__device__ __forceinline__ float2 ffma2(float2 a, float2 b, float2 c) {
    float2 r;
    asm("fma.rn.f32x2 %0, %1, %2, %3;"
        : "=l"(*reinterpret_cast<unsigned long long*>(&r))
        : "l"(*reinterpret_cast<unsigned long long*>(&a)),
          "l"(*reinterpret_cast<unsigned long long*>(&b)),
          "l"(*reinterpret_cast<unsigned long long*>(&c)));
    return r;
}

// ---------------- K1: RevIN stats per (b,v) --------------------------------
__global__ void k_revin(const float* __restrict__ x) {
    int b = blockIdx.x;
    int v = threadIdx.x;      // 64
    int ty = threadIdx.y;     // 8
    __shared__ float ssum[8][64];
    __shared__ float ssq[8][64];
    float s = 0.f, q = 0.f;
    const float* xp = x + (size_t)b*LL*VV + v;
    for (int l = ty; l < LL; l += 8) {
        float val = xp[(size_t)l*VV];
        s += val; q += val*val;
    }
    ssum[ty][v] = s; ssq[ty][v] = q;
    __syncthreads();
    if (ty == 0) {
        for (int j = 1; j < 8; j++) { s += ssum[j][v]; q += ssq[j][v]; }
        float mean = s * (1.0f/LL);
        float var  = q * (1.0f/LL) - mean*mean;
        g_mean[b*VV + v] = mean;
        g_std[b*VV + v]  = sqrtf(var + 1e-5f);
    }
}

// ---------------- K1b: centroid squared norms ------------------------------
__global__ void k_c2(const float* __restrict__ cent) {
    int w = threadIdx.x >> 5, l = threadIdx.x & 31;
    int k = blockIdx.x * 8 + w;
    const float* cp = cent + (size_t)k*DD;
    float s = 0.f;
    #pragma unroll
    for (int q = 0; q < 4; q++) { float c = cp[l + 32*q]; s += c*c; }
    #pragma unroll
    for (int o = 16; o; o >>= 1) s += __shfl_xor_sync(0xffffffffu, s, o);
    if (l == 0) g_c2[k] = s;
}

// ---------------- K2: encode (16->128) + LN + transpose to [bv,d,p] --------
__global__ void __launch_bounds__(256) k_encode(
    const float* __restrict__ x, const float* __restrict__ ew,
    const float* __restrict__ eb, const float* __restrict__ lnw,
    const float* __restrict__ lnb) {
    __shared__ float xv[1024];
    __shared__ float ws[16*128];
    __shared__ float zt[64*128];
    int bv = blockIdx.x; int t = threadIdx.x;
    int b = bv >> 6, v = bv & 63;
    float mean = g_mean[bv], rstd = 1.0f / g_std[bv];
    const float* xp = x + (size_t)b*LL*VV + v;
    for (int i = t; i < 1024; i += 256) xv[i] = (xp[(size_t)i*VV] - mean) * rstd;
    for (int i = t; i < 2048; i += 256) ws[i] = ew[i];
    __syncthreads();
    for (int idx = t; idx < 8192; idx += 256) {
        int p = idx >> 7, d = idx & 127;
        float s = eb[d];
        const float* xq = &xv[p*16];
        #pragma unroll
        for (int i = 0; i < 16; i++) s += xq[i] * ws[i*128 + d];
        zt[idx] = s;
    }
    __syncthreads();
    int w = t >> 5, l = t & 31;
    #pragma unroll
    for (int j = 0; j < 8; j++) {
        int p = w*8 + j;
        float z[4]; float s = 0.f, q = 0.f;
        #pragma unroll
        for (int qq = 0; qq < 4; qq++) {
            z[qq] = zt[p*128 + l + 32*qq];
            s += z[qq]; q += z[qq]*z[qq];
        }
        #pragma unroll
        for (int o = 16; o; o >>= 1) {
            s += __shfl_xor_sync(0xffffffffu, s, o);
            q += __shfl_xor_sync(0xffffffffu, q, o);
        }
        float mu = s * (1.0f/128.0f);
        float rs = rsqrtf(q*(1.0f/128.0f) - mu*mu + 1e-5f);
        #pragma unroll
        for (int qq = 0; qq < 4; qq++) {
            int d = l + 32*qq;
            g_A[((size_t)bv*128 + d)*64 + p] = (z[qq]-mu)*rs*lnw[d] + lnb[d];
        }
    }
}

// ---------------- K3: fused 3-layer MLP (the FLOP king) --------------------
// rows: 64 per block; fc1 64->256 relu; fcm 256->512 relu (chunked by 128);
// fc2 512->32 accumulated across chunks. f32x2 packed FMA throughout.
__global__ void __launch_bounds__(256) k_mlp(
    const float* __restrict__ w1, const float* __restrict__ b1,
    const float* __restrict__ w2, const float* __restrict__ b2,
    const float* __restrict__ w3, const float* __restrict__ b3) {
    extern __shared__ float sm[];
    float* As = sm;               // [64 k][72]        4608
    float* Ws = As + 64*72;       // tile buffer       4096
    float* H1 = Ws + 4096;        // [256 n][68 m]     17408
    float* H2 = H1 + 256*68;      // [128 n][68 m]     8704
    int t = threadIdx.x;
    int row0 = blockIdx.x * 64;

    for (int i = t; i < 64*64; i += 256) {
        int m = i >> 6, k = i & 63;
        As[k*72 + m] = g_A[(size_t)(row0+m)*64 + k];
    }
    __syncthreads();

    // ---- stage 1: H1 = relu(A @ W1 + b1), store transposed [n][m] ----
    {
        int tx = t & 31, ty = t >> 5;
        int cn = tx*8, rm = ty*8;
        float2 acc[8][4];
        #pragma unroll
        for (int i = 0; i < 8; i++)
            #pragma unroll
            for (int j = 0; j < 4; j++) acc[i][j] = make_float2(0.f,0.f);
        for (int kt = 0; kt < 4; kt++) {
            for (int i = t; i < 4096; i += 256) Ws[i] = w1[kt*4096 + i];
            __syncthreads();
            #pragma unroll 4
            for (int k = 0; k < 16; k++) {
                float4 a0 = *(const float4*)&As[(kt*16+k)*72 + rm];
                float4 a1 = *(const float4*)&As[(kt*16+k)*72 + rm + 4];
                float4 wv0 = *(const float4*)&Ws[k*256 + cn];
                float4 wv1 = *(const float4*)&Ws[k*256 + cn + 4];
                float a[8] = {a0.x,a0.y,a0.z,a0.w,a1.x,a1.y,a1.z,a1.w};
                float2 wf[4] = {make_float2(wv0.x,wv0.y), make_float2(wv0.z,wv0.w),
                                make_float2(wv1.x,wv1.y), make_float2(wv1.z,wv1.w)};
                #pragma unroll
                for (int i = 0; i < 8; i++) {
                    float2 ab = make_float2(a[i], a[i]);
                    #pragma unroll
                    for (int j = 0; j < 4; j++) acc[i][j] = ffma2(ab, wf[j], acc[i][j]);
                }
            }
            __syncthreads();
        }
        #pragma unroll
        for (int jj = 0; jj < 8; jj++) {
            int n = cn + jj;
            float bia = b1[n];
            int j = jj >> 1, comp = jj & 1;
            float vals[8];
            #pragma unroll
            for (int i = 0; i < 8; i++) {
                float vv = (comp ? acc[i][j].y : acc[i][j].x) + bia;
                vals[i] = fmaxf(vv, 0.f);
            }
            *(float4*)&H1[n*68 + rm]     = make_float4(vals[0],vals[1],vals[2],vals[3]);
            *(float4*)&H1[n*68 + rm + 4] = make_float4(vals[4],vals[5],vals[6],vals[7]);
        }
        __syncthreads();
    }

    // ---- stage 2+3: chunked fcm + fc2 accumulation ----
    int tx2 = t & 15, ty2 = t >> 4;       // stage2: n=tx2*8, m=ty2*4
    int m3 = t >> 2, tn3 = (t & 3) * 8;   // stage3: m=m3, n=tn3..tn3+7
    float2 oacc[4];
    #pragma unroll
    for (int j = 0; j < 4; j++) oacc[j] = make_float2(0.f,0.f);

    for (int c = 0; c < 4; c++) {
        float2 a2[4][4];
        #pragma unroll
        for (int i = 0; i < 4; i++)
            #pragma unroll
            for (int j = 0; j < 4; j++) a2[i][j] = make_float2(0.f,0.f);
        for (int kt = 0; kt < 16; kt++) {
            for (int i = t; i < 2048; i += 256) {
                int kk = i >> 7, n = i & 127;
                Ws[i] = w2[(size_t)(kt*16+kk)*512 + c*128 + n];
            }
            __syncthreads();
            #pragma unroll 4
            for (int k = 0; k < 16; k++) {
                float4 av  = *(const float4*)&H1[(kt*16+k)*68 + ty2*4];
                float4 wv0 = *(const float4*)&Ws[k*128 + tx2*8];
                float4 wv1 = *(const float4*)&Ws[k*128 + tx2*8 + 4];
                float a[4] = {av.x,av.y,av.z,av.w};
                float2 wf[4] = {make_float2(wv0.x,wv0.y), make_float2(wv0.z,wv0.w),
                                make_float2(wv1.x,wv1.y), make_float2(wv1.z,wv1.w)};
                #pragma unroll
                for (int i = 0; i < 4; i++) {
                    float2 ab = make_float2(a[i], a[i]);
                    #pragma unroll
                    for (int j = 0; j < 4; j++) a2[i][j] = ffma2(ab, wf[j], a2[i][j]);
                }
            }
            __syncthreads();
        }
        // bias+relu, store H2 transposed [n][m]
        #pragma unroll
        for (int jj = 0; jj < 8; jj++) {
            int n = tx2*8 + jj;
            float bia = b2[c*128 + n];
            int j = jj >> 1, comp = jj & 1;
            float vals[4];
            #pragma unroll
            for (int i = 0; i < 4; i++) {
                float vv = (comp ? a2[i][j].y : a2[i][j].x) + bia;
                vals[i] = fmaxf(vv, 0.f);
            }
            *(float4*)&H2[n*68 + ty2*4] = make_float4(vals[0],vals[1],vals[2],vals[3]);
        }
        __syncthreads();
        // load W3 chunk [128][32]
        for (int i = t; i < 4096; i += 256) Ws[i] = w3[c*4096 + i];
        __syncthreads();
        // stage 3 accumulate OUT += H2c @ W3c
        #pragma unroll 4
        for (int k = 0; k < 128; k++) {
            float a = H2[k*68 + m3];
            float4 wv0 = *(const float4*)&Ws[k*32 + tn3];
            float4 wv1 = *(const float4*)&Ws[k*32 + tn3 + 4];
            float2 ab = make_float2(a, a);
            oacc[0] = ffma2(ab, make_float2(wv0.x, wv0.y), oacc[0]);
            oacc[1] = ffma2(ab, make_float2(wv0.z, wv0.w), oacc[1]);
            oacc[2] = ffma2(ab, make_float2(wv1.x, wv1.y), oacc[2]);
            oacc[3] = ffma2(ab, make_float2(wv1.z, wv1.w), oacc[3]);
        }
        __syncthreads();
    }

    // epilogue: + b3, scatter to z_p layout [n=(bv,f)][d]
    int row = row0 + m3;
    int bv32 = (row0 >> 7) * 32;
    int d = row & 127;
    #pragma unroll
    for (int jj = 0; jj < 8; jj++) {
        int f = tn3 + jj;
        int j = jj >> 1, comp = jj & 1;
        float vv = (comp ? oacc[j].y : oacc[j].x) + b3[f];
        g_Zp[(size_t)(bv32 + f)*128 + d] = vv;
    }
}

// ---------------- K4: VQ distances + logits + top5 + softmax gather --------
__global__ void __launch_bounds__(256) k_vq(const float* __restrict__ cent,
                                            float* __restrict__ logits) {
    extern __shared__ float sm[];
    float* Zt  = sm;               // [128 d][68 m]   8704
    float* Cs  = Zt + 8704;        // [128 d][136 k]  17408
    float* z2s = Cs + 17408;       // 64
    float* sval = z2s + 64;        // 64*16*5 = 5120
    int*   sidx = (int*)(sval + 5120);
    float* wsm  = (float*)(sidx + 5120);  // 64*5
    int*   ism  = (int*)(wsm + 320);      // 64*5
    int t = threadIdx.x;
    int n0 = blockIdx.x * 64;

    for (int i = t; i < 64*128; i += 256) {
        int m = i >> 7, d = i & 127;
        Zt[d*68 + m] = g_Zp[(size_t)(n0+m)*128 + d];
    }
    __syncthreads();
    if (t < 64) {
        float s = 0.f;
        for (int d = 0; d < 128; d++) { float vv = Zt[d*68 + t]; s += vv*vv; }
        z2s[t] = s;
    }
    __syncthreads();

    int tx = t & 15, ty = t >> 4;
    int kk = tx*8, mb = ty*4;
    float tv[4][5]; int ti[4][5];
    #pragma unroll
    for (int i = 0; i < 4; i++)
        #pragma unroll
        for (int s5 = 0; s5 < 5; s5++) { tv[i][s5] = 3.0e38f; ti[i][s5] = 0; }

    for (int kt = 0; kt < 8; kt++) {
        for (int i = t; i < 128*128; i += 256) {
            int k = i >> 7, d = i & 127;
            Cs[d*136 + k] = cent[(size_t)(kt*128+k)*128 + d];
        }
        __syncthreads();
        float2 acc[4][4];
        #pragma unroll
        for (int i = 0; i < 4; i++)
            #pragma unroll
            for (int j = 0; j < 4; j++) acc[i][j] = make_float2(0.f,0.f);
        #pragma unroll 4
        for (int d = 0; d < 128; d++) {
            float4 av  = *(const float4*)&Zt[d*68 + mb];
            float4 w0  = *(const float4*)&Cs[d*136 + kk];
            float4 w1  = *(const float4*)&Cs[d*136 + kk + 4];
            float a[4] = {av.x,av.y,av.z,av.w};
            float2 wf[4] = {make_float2(w0.x,w0.y), make_float2(w0.z,w0.w),
                            make_float2(w1.x,w1.y), make_float2(w1.z,w1.w)};
            #pragma unroll
            for (int i = 0; i < 4; i++) {
                float2 ab = make_float2(a[i], a[i]);
                #pragma unroll
                for (int j = 0; j < 4; j++) acc[i][j] = ffma2(ab, wf[j], acc[i][j]);
            }
        }
        // epilogue: dist -> logits + local top5
        #pragma unroll
        for (int i = 0; i < 4; i++) {
            int n = n0 + mb + i;
            float z2v = z2s[mb + i];
            float vout[8];
            #pragma unroll
            for (int jj = 0; jj < 8; jj++) {
                int k = kt*128 + kk + jj;
                int j = jj >> 1, comp = jj & 1;
                float zc = comp ? acc[i][j].y : acc[i][j].x;
                float dist = z2v + g_c2[k] - 2.0f*zc;
                vout[jj] = -dist;
                if (dist < tv[i][4]) {
                    tv[i][4] = dist; ti[i][4] = k;
                    #pragma unroll
                    for (int s5 = 4; s5 > 0; s5--) {
                        if (tv[i][s5] < tv[i][s5-1]) {
                            float tf = tv[i][s5]; tv[i][s5] = tv[i][s5-1]; tv[i][s5-1] = tf;
                            int tk = ti[i][s5]; ti[i][s5] = ti[i][s5-1]; ti[i][s5-1] = tk;
                        }
                    }
                }
            }
            float* lp = logits + (size_t)n*1024 + kt*128 + kk;
            *(float4*)lp     = make_float4(vout[0],vout[1],vout[2],vout[3]);
            *(float4*)(lp+4) = make_float4(vout[4],vout[5],vout[6],vout[7]);
        }
        __syncthreads();
    }

    // dump local top5 and merge per row
    #pragma unroll
    for (int i = 0; i < 4; i++) {
        int r = mb + i;
        #pragma unroll
        for (int s5 = 0; s5 < 5; s5++) {
            sval[r*80 + tx*5 + s5] = tv[i][s5];
            sidx[r*80 + tx*5 + s5] = ti[i][s5];
        }
    }
    __syncthreads();
    if (t < 64) {
        float mv[5]; int mi[5];
        #pragma unroll
        for (int s5 = 0; s5 < 5; s5++) { mv[s5] = 3.0e38f; mi[s5] = 0; }
        for (int c = 0; c < 80; c++) {
            float dv = sval[t*80 + c]; int ki = sidx[t*80 + c];
            if (dv < mv[4]) {
                mv[4] = dv; mi[4] = ki;
                #pragma unroll
                for (int s5 = 4; s5 > 0; s5--) {
                    if (mv[s5] < mv[s5-1]) {
                        float tf = mv[s5]; mv[s5] = mv[s5-1]; mv[s5-1] = tf;
                        int tk = mi[s5]; mi[s5] = mi[s5-1]; mi[s5-1] = tk;
                    }
                }
            }
        }
        float m0 = mv[0];
        float wv[5]; float wsum = 0.f;
        #pragma unroll
        for (int j = 0; j < 5; j++) { wv[j] = expf(m0 - mv[j]); wsum += wv[j]; }
        float inv = 1.0f / wsum;
        #pragma unroll
        for (int j = 0; j < 5; j++) { wsm[t*5 + j] = wv[j]*inv; ism[t*5 + j] = mi[j]; }
    }
    __syncthreads();

    // weighted codebook gather -> z_code
    int w = t >> 5, l = t & 31;
    for (int r = w; r < 64; r += 8) {
        float wg[5]; int id[5];
        #pragma unroll
        for (int j = 0; j < 5; j++) { wg[j] = wsm[r*5 + j]; id[j] = ism[r*5 + j]; }
        int dbase = l*4;
        float4 o = make_float4(0.f,0.f,0.f,0.f);
        #pragma unroll
        for (int j = 0; j < 5; j++) {
            float4 cv = *(const float4*)&cent[(size_t)id[j]*128 + dbase];
            o.x += wg[j]*cv.x; o.y += wg[j]*cv.y;
            o.z += wg[j]*cv.z; o.w += wg[j]*cv.w;
        }
        *(float4*)&g_Zcode[(size_t)(n0+r)*128 + dbase] = o;
    }
}

// ---------------- K5: residual fusion + LN + decode + denorm ---------------
__global__ void __launch_bounds__(256) k_fuse(
    const float* __restrict__ fw, const float* __restrict__ fb,
    const float* __restrict__ flnw, const float* __restrict__ flnb,
    const float* __restrict__ dw, const float* __restrict__ db,
    float* __restrict__ out) {
    extern __shared__ float sm[];
    float* Ws  = sm;            // 128*128 = 16384
    float* Zps = Ws + 16384;    // 32*128 = 4096
    float* dws = Zps + 4096;    // 128*16 = 2048
    float* Fs  = dws + 2048;    // 8*128 = 1024
    int t = threadIdx.x;
    int bv = blockIdx.x;
    int b = bv >> 6, v = bv & 63;
    for (int i = t; i < 16384; i += 256) Ws[i] = fw[i];
    for (int i = t; i < 4096; i += 256) Zps[i] = g_Zp[(size_t)bv*4096 + i];
    for (int i = t; i < 2048; i += 256) dws[i] = dw[i];
    __syncthreads();
    int w = t >> 5, l = t & 31;
    float stdv = g_std[bv], meanv = g_mean[bv];
    for (int f = w; f < 32; f += 8) {
        float acc4[4];
        #pragma unroll
        for (int q = 0; q < 4; q++) acc4[q] = fb[l + 32*q];
        const float* zrow = &Zps[f*128];
        for (int e = 0; e < 128; e++) {
            float z = zrow[e];
            const float* wr = &Ws[e*128];
            #pragma unroll
            for (int q = 0; q < 4; q++) acc4[q] += z * wr[l + 32*q];
        }
        size_t nrow = (size_t)(bv*32 + f)*128;
        float s = 0.f, qq = 0.f;
        #pragma unroll
        for (int q = 0; q < 4; q++) {
            float val = fmaxf(acc4[q], 0.f) + g_Zcode[nrow + l + 32*q];
            acc4[q] = val;
            s += val; qq += val*val;
        }
        #pragma unroll
        for (int o = 16; o; o >>= 1) {
            s  += __shfl_xor_sync(0xffffffffu, s,  o);
            qq += __shfl_xor_sync(0xffffffffu, qq, o);
        }
        float mu = s * (1.0f/128.0f);
        float rs = rsqrtf(qq*(1.0f/128.0f) - mu*mu + 1e-5f);
        #pragma unroll
        for (int q = 0; q < 4; q++) {
            int d = l + 32*q;
            Fs[w*128 + d] = (acc4[q]-mu)*rs*flnw[d] + flnb[d];
        }
        __syncwarp();
        if (l < 16) {
            float r = db[l];
            #pragma unroll 8
            for (int d = 0; d < 128; d++) r += Fs[w*128 + d] * dws[d*16 + l];
            out[(size_t)b*512*64 + (size_t)(f*16 + l)*64 + v] = r*stdv + meanv;
        }
        __syncwarp();
    }
}

// ---------------- launch ---------------------------------------------------
extern "C" void kernel_launch(void* const* d_in, const int* in_sizes, int n_in,
                              void* d_out, int out_size) {
    const float* x      = (const float*)d_in[0];
    const float* cent   = (const float*)d_in[1];
    const float* enc_w  = (const float*)d_in[2];
    const float* enc_b  = (const float*)d_in[3];
    const float* ln_w   = (const float*)d_in[4];
    const float* ln_b   = (const float*)d_in[5];
    const float* fc1_w  = (const float*)d_in[6];
    const float* fc1_b  = (const float*)d_in[7];
    const float* fcm_w  = (const float*)d_in[8];
    const float* fcm_b  = (const float*)d_in[9];
    const float* fc2_w  = (const float*)d_in[10];
    const float* fc2_b  = (const float*)d_in[11];
    const float* fuse_w = (const float*)d_in[12];
    const float* fuse_b = (const float*)d_in[13];
    const float* fln_w  = (const float*)d_in[14];
    const float* fln_b  = (const float*)d_in[15];
    const float* dec_w  = (const float*)d_in[16];
    const float* dec_b  = (const float*)d_in[17];

    float* out    = (float*)d_out;
    float* logits = out + (size_t)BB*512*VV;   // outputs first, then logits

    int sm3 = (64*72 + 4096 + 256*68 + 128*68) * 4;            // 139264
    int sm4 = (8704 + 17408 + 64 + 5120 + 5120 + 320 + 320)*4; // 148224
    int sm5 = (16384 + 4096 + 2048 + 1024) * 4;                // 94208
    cudaFuncSetAttribute(k_mlp,  cudaFuncAttributeMaxDynamicSharedMemorySize, sm3);
    cudaFuncSetAttribute(k_vq,   cudaFuncAttributeMaxDynamicSharedMemorySize, sm4);
    cudaFuncSetAttribute(k_fuse, cudaFuncAttributeMaxDynamicSharedMemorySize, sm5);

    k_revin<<<BB, dim3(64,8)>>>(x);
    k_c2<<<KK/8, 256>>>(cent);
    k_encode<<<BB*VV, 256>>>(x, enc_w, enc_b, ln_w, ln_b);
    k_mlp<<<NROW/64, 256, sm3>>>(fc1_w, fc1_b, fcm_w, fcm_b, fc2_w, fc2_b);
    k_vq<<<NVQ/64, 256, sm4>>>(cent, logits);
    k_fuse<<<BB*VV, 256, sm5>>>(fuse_w, fuse_b, fln_w, fln_b, dec_w, dec_b, out);
}